// round 4
// baseline (speedup 1.0000x reference)
#include <cuda_runtime.h>
#include <math.h>

#define BB 8
#define NN 2048
#define FD 256
#define KK 205          // int(2048*0.1)+1
#define ACAP 320        // active-column capacity (expected ~205)
#define NNZCAP 256      // nnz-per-row capacity (expected ~41)

// ---- output layout (concatenated f32): x_c | coarse | S | topi ----
#define OFF_XC 0ULL
#define OFF_CO 4194304ULL                       // 8*2048*256
#define OFF_S  (4194304ULL + 33554432ULL)       // + 8*2048*2048
#define OFF_TI (4194304ULL + 2ULL*33554432ULL)  // + 8*2048*2048

// ---- device scratch (static globals; no runtime allocation) ----
__device__ float g_dg   [BB*NN];
__device__ float g_mask [BB*NN];
__device__ float g_y    [BB*NN];
__device__ float g_alpha[BB*NN];
__device__ float g_ca   [BB*NN];
__device__ int   g_cnt  [BB*NN];
__device__ int   g_col  [(size_t)BB*NN*NNZCAP];
__device__ float g_val  [(size_t)BB*NN*NNZCAP];
__device__ int   g_aidx [BB*ACAP];
__device__ int   g_acnt [BB];
__device__ int   g_cmap [BB*NN];
__device__ float g_Sc   [(size_t)BB*NN*ACAP];
__device__ float g_Tt   [(size_t)BB*NN*ACAP];
__device__ float g_cact [(size_t)BB*ACAP*ACAP];

// ---------------------------------------------------------------
// K1: per adj row: rowsum, dg, mask, and ordered CSR compaction.
// One block (256 thr) per row; deterministic (scan-based, no atomics).
// ---------------------------------------------------------------
__global__ void k_rowstats(const float* __restrict__ adj) {
    int row = blockIdx.x;
    int t = threadIdx.x;
    const float* ar = adj + (size_t)row * NN;

    float v[8];
    int base = t * 8;
    float4 u0 = ((const float4*)ar)[t * 2];
    float4 u1 = ((const float4*)ar)[t * 2 + 1];
    v[0]=u0.x; v[1]=u0.y; v[2]=u0.z; v[3]=u0.w;
    v[4]=u1.x; v[5]=u1.y; v[6]=u1.z; v[7]=u1.w;

    float s = 0.f; int c = 0;
    #pragma unroll
    for (int i = 0; i < 8; i++) { s += v[i]; if (v[i] != 0.f) c++; }

    __shared__ float sr[256];
    __shared__ int   sc[256];
    sr[t] = s; sc[t] = c;
    __syncthreads();

    // tree sum for rowsum
    for (int o = 128; o > 0; o >>= 1) {
        if (t < o) sr[t] += sr[t + o];
        __syncthreads();
    }
    // inclusive scan for compaction offsets (column-ascending order)
    for (int o = 1; o < 256; o <<= 1) {
        int mine = sc[t];
        int add  = (t >= o) ? sc[t - o] : 0;
        __syncthreads();
        sc[t] = mine + add;
        __syncthreads();
    }
    int total = sc[255];
    int pos   = sc[t] - c;
    size_t ob = (size_t)row * NNZCAP;
    #pragma unroll
    for (int i = 0; i < 8; i++) {
        if (v[i] != 0.f) {
            if (pos < NNZCAP) { g_col[ob + pos] = base + i; g_val[ob + pos] = v[i]; }
            pos++;
        }
    }
    if (t == 0) {
        float rs = sr[0];
        g_cnt[row]  = (total < NNZCAP) ? total : NNZCAP;
        g_dg[row]   = 1.f / sqrtf(rs + 1.f);   // = d = dg (rowsum+1 >= 1 so clip no-op)
        g_mask[row] = (rs > 0.f) ? 1.f : 0.f;
    }
}

// K2: y[n] = x[n,:] . W  (one warp per row)
__global__ void k_y(const float* __restrict__ x, const float* __restrict__ W) {
    int row  = blockIdx.x * 8 + (threadIdx.x >> 5);
    int lane = threadIdx.x & 31;
    const float* xr = x + (size_t)row * FD;
    float s = 0.f;
    #pragma unroll
    for (int f = lane; f < FD; f += 32) s += xr[f] * W[f];
    #pragma unroll
    for (int o = 16; o > 0; o >>= 1) s += __shfl_down_sync(0xffffffffu, s, o);
    if (lane == 0) g_y[row] = s;
}

// K3: alpha[n] = sigmoid( (dg_n*(sum_m A_hat[n,m] dg_m y_m) + b)^2 )  via sparse row
__global__ void k_alpha(const float* __restrict__ bptr) {
    int row  = blockIdx.x * 8 + (threadIdx.x >> 5);
    int lane = threadIdx.x & 31;
    int nb   = (row >> 11) << 11;
    int cnt  = g_cnt[row];
    size_t base = (size_t)row * NNZCAP;
    float z = 0.f;
    for (int e = lane; e < cnt; e += 32) {
        int nc = nb + g_col[base + e];
        z += g_val[base + e] * g_dg[nc] * g_y[nc];
    }
    #pragma unroll
    for (int o = 16; o > 0; o >>= 1) z += __shfl_down_sync(0xffffffffu, z, o);
    if (lane == 0) {
        float dgn = g_dg[row];
        float ap  = dgn * (z + dgn * g_y[row]) + bptr[0];  // identity diag term
        float tt  = ap * ap;
        g_alpha[row] = 1.f / (1.f + expf(-tt));
    }
}

// K4: per batch: full bitonic sort (val desc, idx asc == lax.top_k tie-break),
// cut, topi out, cut_alpha, active list (ascending j) + colmap.
__global__ void k_topk(float* __restrict__ out, long long out_size) {
    int b = blockIdx.x;
    int t = threadIdx.x;  // 1024
    __shared__ unsigned long long key[NN];
    __shared__ int scn[1024];
    __shared__ float s_cut;

    for (int i = t; i < NN; i += 1024) {
        unsigned vb = __float_as_uint(g_alpha[b * NN + i]);  // alpha in (0.5,1): positive, bit-order == value-order
        key[i] = ((unsigned long long)(0xFFFFFFFFu - vb) << 32) | (unsigned)i;
    }
    __syncthreads();
    for (int sz = 2; sz <= NN; sz <<= 1) {
        for (int st = sz >> 1; st > 0; st >>= 1) {
            for (int i = t; i < NN; i += 1024) {
                int p = i ^ st;
                if (p > i) {
                    bool up = ((i & sz) == 0);
                    unsigned long long a = key[i], c = key[p];
                    if ((a > c) == up) { key[i] = c; key[p] = a; }
                }
            }
            __syncthreads();
        }
    }
    if (t == 0) {
        unsigned vb = 0xFFFFFFFFu - (unsigned)(key[KK - 1] >> 32);
        s_cut = __uint_as_float(vb);
    }
    if (t < KK) {
        int idx = (int)(key[t] & 0xFFFFFFFFULL);
        long long o = (long long)OFF_TI + (long long)b * KK + t;
        if (o < out_size) out[o] = (float)idx;
    }
    __syncthreads();
    float cut = s_cut;

    int j0 = 2 * t, j1 = 2 * t + 1;
    float ca0 = fmaxf((g_alpha[b * NN + j0] + 1e-7f) - cut, 0.f);
    float ca1 = fmaxf((g_alpha[b * NN + j1] + 1e-7f) - cut, 0.f);
    g_ca[b * NN + j0] = ca0;
    g_ca[b * NN + j1] = ca1;
    int p0 = ca0 > 0.f ? 1 : 0, p1 = ca1 > 0.f ? 1 : 0;
    scn[t] = p0 + p1;
    __syncthreads();
    for (int o = 1; o < 1024; o <<= 1) {
        int mine = scn[t];
        int add  = (t >= o) ? scn[t - o] : 0;
        __syncthreads();
        scn[t] = mine + add;
        __syncthreads();
    }
    int excl = scn[t] - (p0 + p1);
    if (p0) { int pos = excl;      if (pos < ACAP) { g_cmap[b*NN+j0] = pos; g_aidx[b*ACAP+pos] = j0; } else g_cmap[b*NN+j0] = -1; }
    else g_cmap[b * NN + j0] = -1;
    if (p1) { int pos = excl + p0; if (pos < ACAP) { g_cmap[b*NN+j1] = pos; g_aidx[b*ACAP+pos] = j1; } else g_cmap[b*NN+j1] = -1; }
    else g_cmap[b * NN + j1] = -1;
    if (t == 1023) g_acnt[b] = (scn[1023] < ACAP) ? scn[1023] : ACAP;
}

// K5: build S row (dense write) + compact Sc over active columns.
__global__ void k_S(float* __restrict__ out) {
    __shared__ float srow[NN];
    __shared__ float red[256];
    int row = blockIdx.x, t = threadIdx.x;
    int b = row >> 11, i = row & 2047, nb = b << 11;

    for (int j = t; j < NN; j += 256) srow[j] = 0.f;
    __syncthreads();

    int cnt = g_cnt[row];
    size_t base = (size_t)row * NNZCAP;
    for (int e = t; e < cnt; e += 256) {
        int c = g_col[base + e];
        int nc = nb + c;
        srow[c] = g_val[base + e] * g_dg[nc] * g_ca[nc];
    }
    __syncthreads();
    float dgi = g_dg[row];
    if (t == 0) srow[i] += dgi * g_ca[row];  // A_hat identity diagonal
    __syncthreads();

    float s = 0.f;
    for (int j = t; j < NN; j += 256) s += srow[j];
    red[t] = s;
    __syncthreads();
    for (int o = 128; o > 0; o >>= 1) {
        if (t < o) red[t] += red[t + o];
        __syncthreads();
    }
    float factor = g_mask[row] * dgi;              // S_ij = factor * srow_j
    float denom  = fmaxf(factor * red[0], 1e-12f); // clip(|S|.sum, 1e-12)
    float scale  = factor / denom;

    size_t ob = OFF_S + (size_t)row * NN;
    for (int j = t; j < NN; j += 256) out[ob + j] = srow[j] * scale;

    int AC = g_acnt[b];
    size_t sb = (size_t)row * ACAP;
    for (int a = t; a < AC; a += 256) g_Sc[sb + a] = srow[g_aidx[b * ACAP + a]] * scale;
}

// K6: x_c[m,:] = sum_{n in nbr(m) U {m}} Sc[n,a(m)] * x[n,:]  (zeros elsewhere)
__global__ void k_xc(const float* __restrict__ x, float* __restrict__ out) {
    int row = blockIdx.x, t = threadIdx.x;
    int b = row >> 11, m = row & 2047, nb = b << 11;
    int a = g_cmap[row];
    float acc = 0.f;
    if (a >= 0) {
        int cnt = g_cnt[row];
        size_t base = (size_t)row * NNZCAP;
        bool hasSelf = false;
        for (int e = 0; e < cnt; e++) {
            int c = g_col[base + e];
            int nc = nb + c;
            if (c == m) hasSelf = true;
            float w = g_Sc[(size_t)nc * ACAP + a];
            acc += w * x[(size_t)nc * FD + t];
        }
        if (!hasSelf) {
            float w = g_Sc[(size_t)row * ACAP + a];
            acc += w * x[(size_t)row * FD + t];
        }
    }
    out[OFF_XC + (size_t)row * FD + t] = acc;
}

// K7: Tt[k,a] = sum_{n in nbr(k)} adj[n,k] * Sc[n,a]   (adj symmetric -> row-k list)
__global__ void k_T() {
    int row = blockIdx.x, t = threadIdx.x;
    int b = row >> 11, nb = b << 11;
    int AC = g_acnt[b];
    int cnt = g_cnt[row];
    size_t base = (size_t)row * NNZCAP;
    float a0 = 0.f, a1 = 0.f;
    bool h1 = (t + 256) < AC;
    for (int e = 0; e < cnt; e++) {
        int c = g_col[base + e];
        float v = g_val[base + e];
        size_t sb = (size_t)(nb + c) * ACAP;
        a0 += v * g_Sc[sb + t];
        if (h1) a1 += v * g_Sc[sb + t + 256];
    }
    size_t tb = (size_t)row * ACAP;
    if (t < AC) g_Tt[tb + t] = a0;
    if (h1)     g_Tt[tb + t + 256] = a1;
}

// K8: coarse_act[a,c] = sum_{k in nbr(j_c) U {j_c}} Tt[k,a] * Sc[k,c]
__global__ void k_cact() {
    int bc = blockIdx.x;
    int b = bc / ACAP, c = bc % ACAP;
    int AC = g_acnt[b];
    if (c >= AC) return;
    int t = threadIdx.x;
    int j = g_aidx[b * ACAP + c];
    int nb = b << 11, rowj = nb + j;
    int cnt = g_cnt[rowj];
    size_t base = (size_t)rowj * NNZCAP;
    float a0 = 0.f, a1 = 0.f;
    bool h1 = (t + 256) < AC;
    bool hasSelf = false;
    for (int e = 0; e < cnt; e++) {
        int k = g_col[base + e];
        if (k == j) hasSelf = true;
        size_t kb = (size_t)(nb + k) * ACAP;
        float w = g_Sc[kb + c];
        if (w != 0.f) {
            a0 += w * g_Tt[kb + t];
            if (h1) a1 += w * g_Tt[kb + t + 256];
        }
    }
    if (!hasSelf) {
        size_t kb = (size_t)rowj * ACAP;
        float w = g_Sc[kb + c];
        if (w != 0.f) {
            a0 += w * g_Tt[kb + t];
            if (h1) a1 += w * g_Tt[kb + t + 256];
        }
    }
    size_t cb = (size_t)b * ACAP * ACAP;
    if (t < AC) g_cact[cb + (size_t)t * ACAP + c] = a0;
    if (h1)     g_cact[cb + (size_t)(t + 256) * ACAP + c] = a1;
}

// K9: dense coarse write with floor quantization.
__global__ void k_cwrite(float* __restrict__ out) {
    int row = blockIdx.x, t = threadIdx.x;
    int b = row >> 11;
    int a = g_cmap[row];
    size_t ob = OFF_CO + (size_t)row * NN;
    if (a < 0) {
        for (int j = t; j < NN; j += 256) out[ob + j] = 0.f;
        return;
    }
    const float* crow = g_cact + (size_t)b * ACAP * ACAP + (size_t)a * ACAP;
    const int*   cm   = g_cmap + (b << 11);
    for (int j = t; j < NN; j += 256) {
        int c = cm[j];
        float v = 0.f;
        if (c >= 0) v = floorf(crow[c] * 10000.0f) / 10000.0f;
        out[ob + j] = v;
    }
}

extern "C" void kernel_launch(void* const* d_in, const int* in_sizes, int n_in,
                              void* d_out, int out_size) {
    const float* x    = (const float*)d_in[0];
    const float* adj  = (const float*)d_in[1];
    const float* W    = (const float*)d_in[2];
    const float* bptr = (const float*)d_in[3];
    float* out = (float*)d_out;

    k_rowstats<<<BB * NN, 256>>>(adj);
    k_y      <<<BB * NN / 8, 256>>>(x, W);
    k_alpha  <<<BB * NN / 8, 256>>>(bptr);
    k_topk   <<<BB, 1024>>>(out, (long long)out_size);
    k_S      <<<BB * NN, 256>>>(out);
    k_xc     <<<BB * NN, 256>>>(x, out);
    k_T      <<<BB * NN, 256>>>();
    k_cact   <<<BB * ACAP, 256>>>();
    k_cwrite <<<BB * NN, 256>>>(out);
}

// round 5
// speedup vs baseline: 1.0295x; 1.0295x over previous
#include <cuda_runtime.h>
#include <math.h>

#define BB 8
#define NN 2048
#define FD 256
#define KK 205          // int(2048*0.1)+1
#define ACAP 320        // active-column capacity (expected ~205)
#define NNZCAP 256      // nnz-per-row capacity (expected ~41, max ~70)
#define SCCAP 48        // active entries per Sc row (expected ~4, max ~16)
#define NWORD 10        // ACAP/32 bitmask words

// ---- output layout (concatenated f32): x_c | coarse | S | topi ----
#define OFF_XC 0ULL
#define OFF_CO 4194304ULL                 // 8*2048*256
#define OFF_S  37748736ULL                // + 8*2048*2048
#define OFF_TI 71303168ULL                // + 8*2048*2048

// ---- device scratch ----
__device__ float    g_dg   [BB*NN];
__device__ float    g_mask [BB*NN];
__device__ float    g_y    [BB*NN];
__device__ float    g_alpha[BB*NN];
__device__ float    g_ca   [BB*NN];
__device__ int      g_cnt  [BB*NN];
__device__ int      g_col  [(size_t)BB*NN*NNZCAP];
__device__ float    g_val  [(size_t)BB*NN*NNZCAP];
__device__ int      g_aidx [BB*ACAP];
__device__ int      g_acnt [BB];
__device__ int      g_cmap [BB*NN];
__device__ float    g_scvals[(size_t)BB*NN*SCCAP];   // compact Sc values (a-ascending)
__device__ unsigned g_scmask[BB*NN*NWORD];           // bitmask over a
__device__ int      g_scbase[BB*NN*NWORD];           // exclusive popc prefix per word
__device__ float    g_Tt   [(size_t)BB*NN*ACAP];

// Sc[rown, a] lookup via bitmask + popc into compact values.
__device__ __forceinline__ float sc_lookup(int rown, int a) {
    int w = a >> 5, bit = a & 31;
    unsigned m = g_scmask[rown*NWORD + w];
    if (!((m >> bit) & 1u)) return 0.f;
    int pos = g_scbase[rown*NWORD + w] + __popc(m & ((1u << bit) - 1u));
    return g_scvals[(size_t)rown*SCCAP + pos];
}

// K0: zero-fill x_c | coarse | S regions (285MB) at stream rate.
__global__ void k_fill(float4* __restrict__ out4) {
    const size_t n = OFF_TI / 4;
    size_t i = (size_t)blockIdx.x * blockDim.x + threadIdx.x;
    size_t stride = (size_t)gridDim.x * blockDim.x;
    float4 z = make_float4(0.f, 0.f, 0.f, 0.f);
    for (; i < n; i += stride) out4[i] = z;
}

// K1: per adj row: rowsum, dg, mask, ordered CSR compaction (ballot/shfl).
__global__ void k_rowstats(const float* __restrict__ adj) {
    int row = blockIdx.x;
    int t = threadIdx.x;               // 256
    int lane = t & 31, w = t >> 5;
    const float* ar = adj + (size_t)row * NN;

    float v[8];
    float4 u0 = ((const float4*)ar)[t * 2];
    float4 u1 = ((const float4*)ar)[t * 2 + 1];
    v[0]=u0.x; v[1]=u0.y; v[2]=u0.z; v[3]=u0.w;
    v[4]=u1.x; v[5]=u1.y; v[6]=u1.z; v[7]=u1.w;

    float s = 0.f; int c = 0; unsigned em = 0;
    #pragma unroll
    for (int i = 0; i < 8; i++) { s += v[i]; if (v[i] != 0.f) { c++; em |= 1u << i; } }

    // warp inclusive scan of counts + warp sum
    int csc = c;
    #pragma unroll
    for (int o = 1; o < 32; o <<= 1) {
        int n = __shfl_up_sync(0xffffffffu, csc, o);
        if (lane >= o) csc += n;
    }
    float ss = s;
    #pragma unroll
    for (int o = 16; o > 0; o >>= 1) ss += __shfl_xor_sync(0xffffffffu, ss, o);

    __shared__ int   wtot[8];
    __shared__ float wsum[8];
    __shared__ int   wbase[9];
    __shared__ float s_rs;
    if (lane == 31) wtot[w] = csc;
    if (lane == 0)  wsum[w] = ss;
    __syncthreads();
    if (t == 0) {
        int acc = 0; float rs = 0.f;
        #pragma unroll
        for (int k = 0; k < 8; k++) { wbase[k] = acc; acc += wtot[k]; rs += wsum[k]; }
        wbase[8] = acc; s_rs = rs;
    }
    __syncthreads();

    int pos = wbase[w] + csc - c;
    size_t ob = (size_t)row * NNZCAP;
    int basecol = t * 8;
    #pragma unroll
    for (int i = 0; i < 8; i++) {
        if ((em >> i) & 1u) {
            if (pos < NNZCAP) { g_col[ob + pos] = basecol + i; g_val[ob + pos] = v[i]; }
            pos++;
        }
    }
    if (t == 0) {
        int total = wbase[8];
        float rs = s_rs;
        g_cnt[row]  = (total < NNZCAP) ? total : NNZCAP;
        g_dg[row]   = 1.f / sqrtf(rs + 1.f);
        g_mask[row] = (rs > 0.f) ? 1.f : 0.f;
    }
}

// K2: y[n] = x[n,:] . W  (one warp per row)
__global__ void k_y(const float* __restrict__ x, const float* __restrict__ W) {
    int row  = blockIdx.x * 8 + (threadIdx.x >> 5);
    int lane = threadIdx.x & 31;
    const float* xr = x + (size_t)row * FD;
    float s = 0.f;
    #pragma unroll
    for (int f = lane; f < FD; f += 32) s += xr[f] * W[f];
    #pragma unroll
    for (int o = 16; o > 0; o >>= 1) s += __shfl_down_sync(0xffffffffu, s, o);
    if (lane == 0) g_y[row] = s;
}

// K3: alpha[n] = sigmoid( (dg_n*(sum_m A_hat[n,m] dg_m y_m) + b)^2 )
__global__ void k_alpha(const float* __restrict__ bptr) {
    int row  = blockIdx.x * 8 + (threadIdx.x >> 5);
    int lane = threadIdx.x & 31;
    int nb   = (row >> 11) << 11;
    int cnt  = g_cnt[row];
    size_t base = (size_t)row * NNZCAP;
    float z = 0.f;
    for (int e = lane; e < cnt; e += 32) {
        int nc = nb + g_col[base + e];
        z += g_val[base + e] * g_dg[nc] * g_y[nc];
    }
    #pragma unroll
    for (int o = 16; o > 0; o >>= 1) z += __shfl_down_sync(0xffffffffu, z, o);
    if (lane == 0) {
        float dgn = g_dg[row];
        float ap  = dgn * (z + dgn * g_y[row]) + bptr[0];
        float tt  = ap * ap;
        g_alpha[row] = 1.f / (1.f + expf(-tt));
    }
}

// K4: histogram radix-select (alpha in (0.5,1], fixed exponent -> bits>>13
// monotone), compact candidates of top bins, bitonic-sort 512, exact cut +
// topi + cut_alpha + active list/colmap.
__global__ void k_topk(float* __restrict__ out, long long out_size) {
    int b = blockIdx.x;
    int t = threadIdx.x;  // 1024
    __shared__ int hist[1024];
    __shared__ int scn[1024];
    __shared__ unsigned long long cand[512];
    __shared__ int s_T, s_C;
    __shared__ float s_cut;

    hist[t] = 0;
    if (t == 0) s_C = 0;
    __syncthreads();

    unsigned b0 = __float_as_uint(g_alpha[b * NN + 2*t]);
    unsigned b1 = __float_as_uint(g_alpha[b * NN + 2*t + 1]);
    int bin0 = (int)(b0 >> 13) - 0x1F800; bin0 = bin0 < 0 ? 0 : (bin0 > 1023 ? 1023 : bin0);
    int bin1 = (int)(b1 >> 13) - 0x1F800; bin1 = bin1 < 0 ? 0 : (bin1 > 1023 ? 1023 : bin1);
    atomicAdd(&hist[bin0], 1);
    atomicAdd(&hist[bin1], 1);
    __syncthreads();

    // suffix counts via inclusive scan of reversed hist
    int r = 1023 - t;
    scn[t] = hist[r];
    __syncthreads();
    for (int o = 1; o < 1024; o <<= 1) {
        int mine = scn[t];
        int add  = (t >= o) ? scn[t - o] : 0;
        __syncthreads();
        scn[t] = mine + add;
        __syncthreads();
    }
    int sufi = scn[t];                       // suffix[r]
    int sufn = (t >= 1) ? scn[t - 1] : 0;    // suffix[r+1]
    if (sufi >= KK && sufn < KK) s_T = r;
    __syncthreads();
    int T = s_T;

    if (bin0 >= T) {
        int p = atomicAdd(&s_C, 1);
        if (p < 512) cand[p] = ((unsigned long long)(0xFFFFFFFFu - b0) << 32) | (unsigned)(2*t);
    }
    if (bin1 >= T) {
        int p = atomicAdd(&s_C, 1);
        if (p < 512) cand[p] = ((unsigned long long)(0xFFFFFFFFu - b1) << 32) | (unsigned)(2*t + 1);
    }
    __syncthreads();
    int C = s_C < 512 ? s_C : 512;
    if (t >= C && t < 512) cand[t] = 0xFFFFFFFFFFFFFFFFULL;
    __syncthreads();

    // bitonic sort 512 ascending (smaller key = larger alpha, idx tie-break asc)
    for (int sz = 2; sz <= 512; sz <<= 1) {
        for (int st = sz >> 1; st > 0; st >>= 1) {
            if (t < 512) {
                int p = t ^ st;
                if (p > t) {
                    bool up = ((t & sz) == 0);
                    unsigned long long a = cand[t], c2 = cand[p];
                    if ((a > c2) == up) { cand[t] = c2; cand[p] = a; }
                }
            }
            __syncthreads();
        }
    }

    if (t == 0) {
        unsigned vb = 0xFFFFFFFFu - (unsigned)(cand[KK - 1] >> 32);
        s_cut = __uint_as_float(vb);
    }
    if (t < KK) {
        int idx = (int)(cand[t] & 0xFFFFFFFFULL);
        long long o = (long long)OFF_TI + (long long)b * KK + t;
        if (o < out_size) out[o] = (float)idx;
    }
    __syncthreads();
    float cut = s_cut;

    int j0 = 2*t, j1 = 2*t + 1;
    float ca0 = fmaxf((__uint_as_float(b0) + 1e-7f) - cut, 0.f);
    float ca1 = fmaxf((__uint_as_float(b1) + 1e-7f) - cut, 0.f);
    g_ca[b * NN + j0] = ca0;
    g_ca[b * NN + j1] = ca1;
    int p0 = ca0 > 0.f ? 1 : 0, p1 = ca1 > 0.f ? 1 : 0;
    scn[t] = p0 + p1;
    __syncthreads();
    for (int o = 1; o < 1024; o <<= 1) {
        int mine = scn[t];
        int add  = (t >= o) ? scn[t - o] : 0;
        __syncthreads();
        scn[t] = mine + add;
        __syncthreads();
    }
    int excl = scn[t] - (p0 + p1);
    if (p0) { int pos = excl;      if (pos < ACAP) { g_cmap[b*NN+j0] = pos; g_aidx[b*ACAP+pos] = j0; } else g_cmap[b*NN+j0] = -1; }
    else g_cmap[b * NN + j0] = -1;
    if (p1) { int pos = excl + p0; if (pos < ACAP) { g_cmap[b*NN+j1] = pos; g_aidx[b*ACAP+pos] = j1; } else g_cmap[b*NN+j1] = -1; }
    else g_cmap[b * NN + j1] = -1;
    if (t == 1023) g_acnt[b] = (scn[1023] < ACAP) ? scn[1023] : ACAP;
}

// K5: one thread per row. Build sparse S row (entries where column active,
// A_hat diag merged/inserted in j-ascending order), rowsum, scale; write
// compact Sc (values + bitmask + popc bases) and scatter into dense S.
__global__ void k_S(float* __restrict__ out) {
    int row = blockIdx.x * blockDim.x + threadIdx.x;
    if (row >= BB * NN) return;
    int b = row >> 11, i = row & 2047, nb = b << 11;
    int cnt = g_cnt[row];
    size_t base = (size_t)row * NNZCAP;

    int   aL[SCCAP];
    int   jL[SCCAP];
    float vL[SCCAP];
    int ns = 0;
    float rowsum = 0.f;
    int   selfA  = g_cmap[row];
    float dgi    = g_dg[row];
    float selfVal = dgi * g_ca[row];
    bool selfDone = (selfA < 0);

    for (int e = 0; e < cnt; e++) {
        int j = g_col[base + e];
        if (!selfDone && j > i) {
            if (ns < SCCAP) { aL[ns]=selfA; jL[ns]=i; vL[ns]=selfVal; rowsum+=selfVal; ns++; }
            selfDone = true;
        }
        int nc = nb + j;
        int a = g_cmap[nc];
        if (a < 0) continue;
        float sval = g_val[base + e] * g_dg[nc] * g_ca[nc];
        if (j == i) { sval += selfVal; selfDone = true; }
        if (ns < SCCAP) { aL[ns]=a; jL[ns]=j; vL[ns]=sval; rowsum+=sval; ns++; }
    }
    if (!selfDone && ns < SCCAP) { aL[ns]=selfA; jL[ns]=i; vL[ns]=selfVal; rowsum+=selfVal; ns++; }

    float factor = g_mask[row] * dgi;
    float denom  = fmaxf(factor * rowsum, 1e-12f);
    float scale  = factor / denom;

    unsigned msk[NWORD];
    #pragma unroll
    for (int w = 0; w < NWORD; w++) msk[w] = 0u;
    for (int q = 0; q < ns; q++) msk[aL[q] >> 5] |= 1u << (aL[q] & 31);
    int cum = 0;
    #pragma unroll
    for (int w = 0; w < NWORD; w++) {
        g_scmask[row*NWORD + w] = msk[w];
        g_scbase[row*NWORD + w] = cum;
        cum += __popc(msk[w]);
    }
    size_t vb = (size_t)row * SCCAP;
    size_t ob = OFF_S + (size_t)row * NN;
    for (int q = 0; q < ns; q++) {
        float sv = vL[q] * scale;
        g_scvals[vb + q] = sv;
        out[ob + jL[q]] = sv;      // dense S pre-zeroed by k_fill
    }
}

// K6: x_c for active rows only: x_c[m,:] = sum_{n in nbr(m) U {m}} Sc[n,a]*x[n,:]
__global__ void k_xc(const float* __restrict__ x, float* __restrict__ out) {
    int b = blockIdx.x / ACAP, a = blockIdx.x % ACAP;
    int AC = g_acnt[b];
    if (a >= AC) return;
    int nb = b << 11;
    int m = g_aidx[b * ACAP + a];
    int row = nb + m;
    int cnt = g_cnt[row];
    size_t base = (size_t)row * NNZCAP;

    __shared__ float s_w[NNZCAP];
    __shared__ int   s_nr[NNZCAP];
    __shared__ int   s_diag;
    if (threadIdx.x == 0) s_diag = 0;
    __syncthreads();
    for (int e = threadIdx.x; e < cnt; e += blockDim.x) {
        int j = g_col[base + e];
        int nr = nb + j;
        s_nr[e] = nr;
        s_w[e] = sc_lookup(nr, a);
        if (j == m) s_diag = 1;
    }
    __syncthreads();

    int t = threadIdx.x;  // 256 = FD
    float acc = 0.f;
    for (int e = 0; e < cnt; e++) acc += s_w[e] * x[(size_t)s_nr[e] * FD + t];
    if (!s_diag) acc += sc_lookup(row, a) * x[(size_t)row * FD + t];
    out[OFF_XC + (size_t)row * FD + t] = acc;
}

// K7: Tt[k,a] = sum_{n in nbr(k)} adj[n,k] * Sc[n,a], via sparse Sc:
// per (row, neighbor-chunk): broadcast mask word per warp, predicated
// popc-indexed compact-value load. 320 threads = one a-column each.
__global__ void k_T() {
    int row = blockIdx.x, t = threadIdx.x;   // 320
    int b = row >> 11, nb = b << 11;
    int AC = g_acnt[b];
    int cnt = g_cnt[row];
    size_t base = (size_t)row * NNZCAP;
    int widx = t >> 5, lane = t & 31;
    unsigned ltm = (1u << lane) - 1u;

    __shared__ float    s_v[32];
    __shared__ int      s_rn[32];
    __shared__ unsigned s_m[32 * NWORD];
    __shared__ int      s_bs[32 * NWORD];

    float acc = 0.f;
    for (int c0 = 0; c0 < cnt; c0 += 32) {
        int nch = cnt - c0; if (nch > 32) nch = 32;
        __syncthreads();
        if (t < nch) {
            s_rn[t] = nb + g_col[base + c0 + t];
            s_v[t]  = g_val[base + c0 + t];
        }
        __syncthreads();
        {
            int e = t & 31, w = t >> 5;   // 320 = 32 x 10 exactly
            if (e < nch) {
                int rn = s_rn[e];
                s_m[e*NWORD + w]  = g_scmask[rn*NWORD + w];
                s_bs[e*NWORD + w] = g_scbase[rn*NWORD + w];
            }
        }
        __syncthreads();
        for (int e = 0; e < nch; e++) {
            unsigned m = s_m[e*NWORD + widx];
            if ((m >> lane) & 1u) {
                int pos = s_bs[e*NWORD + widx] + __popc(m & ltm);
                acc += s_v[e] * g_scvals[(size_t)s_rn[e] * SCCAP + pos];
            }
        }
    }
    if (t < AC) g_Tt[(size_t)row * ACAP + t] = acc;
}

// K8: coarse column c: acc[a] = sum_{k in nbr(j_c) U {j_c}} Sc[k,c]*Tt[k,a];
// quantize and scatter directly into dense coarse (pre-zeroed).
__global__ void k_cact(float* __restrict__ out) {
    int b = blockIdx.x / ACAP, c = blockIdx.x % ACAP;
    int AC = g_acnt[b];
    if (c >= AC) return;
    int nb = b << 11;
    int j = g_aidx[b * ACAP + c];
    int rowj = nb + j;
    int cnt = g_cnt[rowj];
    size_t base = (size_t)rowj * NNZCAP;

    __shared__ float s_w[NNZCAP];
    __shared__ int   s_kr[NNZCAP];
    __shared__ int   s_diag;
    if (threadIdx.x == 0) s_diag = 0;
    __syncthreads();
    for (int e = threadIdx.x; e < cnt; e += blockDim.x) {
        int k = g_col[base + e];
        int kr = nb + k;
        s_kr[e] = kr;
        s_w[e] = sc_lookup(kr, c);
        if (k == j) s_diag = 1;
    }
    __syncthreads();

    int t = threadIdx.x;  // 320
    if (t < AC) {
        float acc = 0.f;
        for (int e = 0; e < cnt; e++) {
            float w = s_w[e];
            if (w != 0.f) acc += w * g_Tt[(size_t)s_kr[e] * ACAP + t];
        }
        if (!s_diag) {
            float w = sc_lookup(rowj, c);
            if (w != 0.f) acc += w * g_Tt[(size_t)rowj * ACAP + t];
        }
        float q = floorf(acc * 10000.0f) / 10000.0f;
        out[OFF_CO + (size_t)(nb + g_aidx[b * ACAP + t]) * NN + j] = q;
    }
}

extern "C" void kernel_launch(void* const* d_in, const int* in_sizes, int n_in,
                              void* d_out, int out_size) {
    const float* x    = (const float*)d_in[0];
    const float* adj  = (const float*)d_in[1];
    const float* W    = (const float*)d_in[2];
    const float* bptr = (const float*)d_in[3];
    float* out = (float*)d_out;

    k_fill    <<<8192, 1024>>>((float4*)d_out);
    k_rowstats<<<BB * NN, 256>>>(adj);
    k_y       <<<BB * NN / 8, 256>>>(x, W);
    k_alpha   <<<BB * NN / 8, 256>>>(bptr);
    k_topk    <<<BB, 1024>>>(out, (long long)out_size);
    k_S       <<<(BB * NN) / 128, 128>>>(out);
    k_xc      <<<BB * ACAP, 256>>>(x, out);
    k_T       <<<BB * NN, 320>>>();
    k_cact    <<<BB * ACAP, 320>>>(out);
}